// round 6
// baseline (speedup 1.0000x reference)
#include <cuda_runtime.h>
#include <cuda_bf16.h>
#include <math.h>
#include <stdint.h>

#define NN    64
#define KK    48
#define MM    (NN*KK)      // 3072
#define TOBS  30
#define PREDN 15
#define TSTEPS (TOBS+PREDN)  // 45, t runs 1..44
#define EMB   64
#define NODE  128
#define EDGE  256
#define CNN   512
#define GT    (4*NODE)     // 512
#define GN    (4*EDGE)     // 1024
#define CONC  (NODE+CNN+EDGE) // 896

typedef unsigned long long ULL;

// f32x2 packed math for the (small) target SIMT GEMM
#define PK(d,s)   asm("mov.b64 %0, {%1, %1};" : "=l"(d) : "f"(s))
#define UPK(lo,hi,p) asm("mov.b64 {%0, %1}, %2;" : "=f"(lo), "=f"(hi) : "l"(p))
#define FMA2(c,a,b) asm("fma.rn.f32x2 %0, %1, %2, %0;" : "+l"(c) : "l"(a), "l"(b))

__device__ __forceinline__ uint32_t smem_u32(const void* p){
    uint32_t a; asm("{ .reg .u64 t; cvta.to.shared.u64 t, %1; cvt.u32.u64 %0, t; }" : "=r"(a) : "l"(p)); return a;
}
#define LDMX4(r0,r1,r2,r3,addr) \
    asm volatile("ldmatrix.sync.aligned.m8n8.x4.shared.b16 {%0,%1,%2,%3}, [%4];" \
        : "=r"(r0), "=r"(r1), "=r"(r2), "=r"(r3) : "r"(addr))
#define MMA16816(c0,c1,c2,c3,a0,a1,a2,a3,b0,b1) \
    asm volatile("mma.sync.aligned.m16n8k16.row.col.f32.bf16.bf16.f32 " \
        "{%0,%1,%2,%3}, {%4,%5,%6,%7}, {%8,%9}, {%0,%1,%2,%3};" \
        : "+f"(c0), "+f"(c1), "+f"(c2), "+f"(c3) \
        : "r"(a0), "r"(a1), "r"(a2), "r"(a3), "r"(b0), "r"(b1))

// ---------------- persistent device state ----------------
__device__ float d_thtT[2][NODE*NN];          // target h, transposed [e][n], fp32
__device__ float d_tct[NN*NODE];
__device__ __nv_bfloat16 d_nhHi[2][MM*EDGE];  // nearby h split bf16, [m][e]
__device__ __nv_bfloat16 d_nhLo[2][MM*EDGE];
__device__ float d_nct[MM*EDGE];
__device__ float d_Ht[NN*EDGE];
__device__ float d_Htacc[NN*EDGE];
__device__ float d_cabs[NN*2], d_crel[NN*2], d_cstep[NN*2];
__device__ float d_w[MM];
__device__ int   d_flag;
__device__ int   d_gateTt[TSTEPS];
__device__ int   d_gateNt[TSTEPS];
__device__ float d_currNt[TSTEPS];
// weights
__device__ __nv_bfloat16 d_WNHi[GN*EDGE];     // nearby Whh gate-interleaved [g][k], split bf16
__device__ __nv_bfloat16 d_WNLo[GN*EDGE];
__device__ float d_WhhTT[NODE*GT];            // target Whh transposed [k][g] fp32
__device__ float d_WxN[GN*2], d_bN[GN];
__device__ float d_WxT[GT*2], d_bT[GT];
__device__ float d_imgpart[NN*2];

__device__ __forceinline__ float sigm(float x){ return 1.f/(1.f+expf(-x)); }

// dynamic smem layout for nearby path (bf16, padded rows: 40 elems = 80B)
#define ASTRIDE 40
#define OFF_AHI 0
#define OFF_ALO 10240
#define OFF_BHI 20480
#define OFF_BLO 25600
#define DSMEM_TOTAL 30720

// ---------------- init kernels ----------------
__global__ void k_zero(){
    long i0 = (long)blockIdx.x*blockDim.x + threadIdx.x;
    long st = (long)gridDim.x*blockDim.x;
    uint32_t* hh = (uint32_t*)&d_nhHi[0][0];
    uint32_t* hl = (uint32_t*)&d_nhLo[0][0];
    for(long i=i0;i<(long)MM*EDGE;i+=st){ hh[i]=0u; hl[i]=0u; } // covers both [2][..] bufs
    for(long i=i0;i<(long)MM*EDGE;i+=st) d_nct[i]=0.f;
    float* th = &d_thtT[0][0];
    for(long i=i0;i<2L*NN*NODE;i+=st) th[i]=0.f;
    for(long i=i0;i<(long)NN*NODE;i+=st) d_tct[i]=0.f;
    for(long i=i0;i<(long)NN*EDGE;i+=st){ d_Ht[i]=0.f; d_Htacc[i]=0.f; }
    if(i0<NN*2){ d_cabs[i0]=0.f; d_crel[i0]=0.f; d_cstep[i0]=0.f; }
    if(i0==0) d_flag=0;
}

__global__ void k_tables(const int* __restrict__ thist, const int* __restrict__ nhist){
    int t = blockIdx.x + 1;
    int tid = threadIdx.x;
    __shared__ int s_cnt[256];
    __shared__ int s_any[256];
    int cnt=0, any=0;
    if(t < TOBS){
        for(int m=tid;m<MM;m+=256) cnt += (nhist[m] > (TOBS - t)) ? 1 : 0;
        for(int n=tid;n<NN;n+=256) any |= (thist[n] > (TOBS - t)) ? 1 : 0;
    }else{
        cnt = (tid==0)?MM:0; any = 1;
    }
    s_cnt[tid]=cnt; s_any[tid]=any;
    __syncthreads();
    for(int o=128;o>0;o>>=1){
        if(tid<o){ s_cnt[tid]+=s_cnt[tid+o]; s_any[tid]|=s_any[tid+o]; }
        __syncthreads();
    }
    if(tid==0){
        int gt = s_any[0]?1:0;
        int cn = s_cnt[0];
        d_gateTt[t]=gt; d_gateNt[t]=(gt && cn>0)?1:0; d_currNt[t]=(float)cn;
    }
}

__global__ void k_prep(const float* __restrict__ Whh_n, const float* __restrict__ Wih_n,
                       const float* __restrict__ bih_n, const float* __restrict__ bhh_n,
                       const float* __restrict__ Whh_t, const float* __restrict__ Wih_t,
                       const float* __restrict__ bih_t, const float* __restrict__ bhh_t,
                       const float* __restrict__ W_disp, const float* __restrict__ b_disp,
                       const float* __restrict__ img, const float* __restrict__ W_pred){
    int i0 = blockIdx.x*blockDim.x + threadIdx.x;
    int st = gridDim.x*blockDim.x;
    for(int i=i0;i<GN*EDGE;i+=st){
        int g=i/EDGE, k=i%EDGE; int e=g>>2, q=g&3;
        float v = Whh_n[(q*EDGE+e)*EDGE + k];
        __nv_bfloat16 hi = __float2bfloat16(v);
        d_WNHi[i] = hi;
        d_WNLo[i] = __float2bfloat16(v - __bfloat162float(hi));
    }
    for(int i=i0;i<NODE*GT;i+=st){
        int k=i/GT, g=i%GT; int e=g>>2, q=g&3;
        d_WhhTT[i] = Whh_t[(q*NODE+e)*NODE + k];
    }
    for(int r=i0;r<GN;r+=st){
        int e=r>>2, q=r&3; int o=q*EDGE+e;
        float w0=0.f,w1=0.f,bb=bih_n[o]+bhh_n[o];
        for(int d=0;d<EMB;d++){
            float wi=Wih_n[o*EMB+d];
            w0+=wi*W_disp[d*2]; w1+=wi*W_disp[d*2+1]; bb+=wi*b_disp[d];
        }
        d_WxN[r*2]=w0; d_WxN[r*2+1]=w1; d_bN[r]=bb;
    }
    for(int r=i0;r<GT;r+=st){
        int e=r>>2, q=r&3; int o=q*NODE+e;
        float w0=0.f,w1=0.f,bb=bih_t[o]+bhh_t[o];
        for(int d=0;d<EMB;d++){
            float wi=Wih_t[o*EMB+d];
            w0+=wi*W_disp[d*2]; w1+=wi*W_disp[d*2+1]; bb+=wi*b_disp[d];
        }
        d_WxT[r*2]=w0; d_WxT[r*2+1]=w1; d_bT[r]=bb;
    }
    for(int i=i0;i<NN*2;i+=st){
        int n=i>>1, j=i&1; float s=0.f;
        for(int c=0;c<CNN;c++) s += img[n*CNN+c]*W_pred[j*CONC + NODE + c];
        d_imgpart[i]=s;
    }
}

// =========================================================================
// per-step kernel. bx==0: small serial work (publishes d_flag=t).
// bx 1..384: nearby mma.sync bf16-split GEMM + fused LSTM (M128 x N64g x K256)
// bx 385..388: target SIMT GEMM+LSTM.
// =========================================================================
__global__ void __launch_bounds__(256,3) k_step(int t,
    const float* __restrict__ tabs, const float* __restrict__ trel, const float* __restrict__ tstep,
    const float* __restrict__ nabs_in, const float* __restrict__ nstep_in,
    const int* __restrict__ thist, const int* __restrict__ nhist,
    const float* __restrict__ W_att_t, const float* __restrict__ b_att_t,
    const float* __restrict__ W_att_n, const float* __restrict__ b_att_n,
    const float* __restrict__ W_pred, const float* __restrict__ b_pred,
    float* __restrict__ out)
{
    extern __shared__ __align__(128) char dsm[];
    int bx = blockIdx.x;
    int tid = threadIdx.x;
    int cur=(t-1)&1, nxt=t&1;
    bool obs = (t < TOBS);
    int tc = obs ? t : (TOBS-1);

    if(bx == 0){
        // ------------- small serial work -------------
        __shared__ float s_pred[NN*2];
        int gate_n_prev = (t>=2) ? d_gateNt[t-1] : 0;
        for(int i=tid;i<NN*EDGE;i+=256){
            if(gate_n_prev) d_Ht[i]=d_Htacc[i];
            d_Htacc[i]=0.f;
        }
        __syncthreads();
        if(!obs){
            int item = tid>>1, sub = tid&1;
            int n = item>>1, j = item&1;
            const float* wp = &W_pred[j*CONC];
            const float* hh = &d_Ht[n*EDGE];
            float acc = 0.f;
            for(int e=sub*64;e<sub*64+64;e++) acc += d_thtT[cur][e*NN+n]*wp[e];
            for(int e=sub*128;e<sub*128+128;e++) acc += hh[e]*wp[NODE+CNN+e];
            acc += __shfl_xor_sync(0xffffffffu, acc, 1);
            if(sub==0) s_pred[item] = acc + d_imgpart[item] + b_pred[j];
        }
        __syncthreads();
        if(obs){
            if(tid<NN*2){
                int n=tid>>1, j=tid&1; int off=(n*TOBS+t)*2+j;
                d_cabs[tid]=tabs[off]; d_crel[tid]=trel[off]; d_cstep[tid]=tstep[off];
            }
        }else{
            if(tid<NN*2){
                float p=s_pred[tid];
                d_cabs[tid]+=p;
                float cr=d_crel[tid]+p; d_crel[tid]=cr;
                d_cstep[tid]=p;
                int n=tid>>1, j=tid&1;
                out[(n*PREDN + (t-TOBS))*2 + j] = cr;
            }
        }
        __syncthreads();
        float currNf = d_currNt[t];
        int n = tid>>2, s = tid&3;
        float crel0=d_crel[n*2], crel1=d_crel[n*2+1];
        float p0=0.f,p1=0.f,p2=0.f;
        for(int a=s*16;a<s*16+16;a++){
            float atv = W_att_t[a*2]*crel0 + W_att_t[a*2+1]*crel1 + b_att_t[a];
            p0 += atv*W_att_n[a*2];
            p1 += atv*W_att_n[a*2+1];
            p2 += atv*b_att_n[a];
        }
        #pragma unroll
        for(int o=1;o<4;o<<=1){
            p0 += __shfl_xor_sync(0xffffffffu,p0,o);
            p1 += __shfl_xor_sync(0xffffffffu,p1,o);
            p2 += __shfl_xor_sync(0xffffffffu,p2,o);
        }
        float cab0=d_cabs[n*2], cab1=d_cabs[n*2+1];
        float sc[12], mf[12];
        #pragma unroll
        for(int kk=0;kk<12;kk++){
            int m = n*KK + s*12+kk;
            int off = (m*TOBS+tc)*2;
            float dx=nabs_in[off]-cab0, dy=nabs_in[off+1]-cab1;
            float mv = obs ? ((nhist[m] > (TOBS - t)) ? 1.f : 0.f) : 1.f;
            mf[kk]=mv;
            sc[kk]=(dx*p0+dy*p1+p2)*currNf*0.125f*mv;
        }
        float mx = sc[0];
        #pragma unroll
        for(int kk=1;kk<12;kk++) mx=fmaxf(mx,sc[kk]);
        #pragma unroll
        for(int o=1;o<4;o<<=1) mx = fmaxf(mx, __shfl_xor_sync(0xffffffffu,mx,o));
        float dn = 0.f;
        #pragma unroll
        for(int kk=0;kk<12;kk++) dn += expf(sc[kk]-mx)*mf[kk];
        #pragma unroll
        for(int o=1;o<4;o<<=1) dn += __shfl_xor_sync(0xffffffffu,dn,o);
        dn += 1e-6f;
        #pragma unroll
        for(int kk=0;kk<12;kk++){
            int m = n*KK + s*12+kk;
            d_w[m] = expf(sc[kk]-mx)*mf[kk]/dn;
        }
        __threadfence();
        __syncthreads();
        if(tid==0) atomicExch(&d_flag, t);
        return;
    }

    if(bx <= 384){
        // ================= nearby: mma.sync split-bf16 GEMM + fused LSTM =================
        const int bi = bx-1;
        int rowTile = bi % 24, colTile = bi / 24;   // 24 M-tiles x 16 N-tiles(64 gates)
        int m0 = rowTile*128, g0 = colTile*64, e0c = colTile*16;
        const __nv_bfloat16* hHi = d_nhHi[cur];
        const __nv_bfloat16* hLo = d_nhLo[cur];
        int wid = tid>>5, lane = tid&31;
        int tig = lane&3, gid = lane>>2;

        __nv_bfloat16* sAhi = (__nv_bfloat16*)(dsm + OFF_AHI);
        __nv_bfloat16* sAlo = (__nv_bfloat16*)(dsm + OFF_ALO);
        __nv_bfloat16* sBhi = (__nv_bfloat16*)(dsm + OFF_BHI);
        __nv_bfloat16* sBlo = (__nv_bfloat16*)(dsm + OFF_BLO);
        uint32_t uAhi = smem_u32(sAhi), uAlo = smem_u32(sAlo);
        uint32_t uBhi = smem_u32(sBhi), uBlo = smem_u32(sBlo);

        float C[8][4];
        #pragma unroll
        for(int j=0;j<8;j++){ C[j][0]=0.f; C[j][1]=0.f; C[j][2]=0.f; C[j][3]=0.f; }

        // ldmatrix source addresses (per warp/lane), row-major padded ASTRIDE
        uint32_t aAddrBase = uAhi + (uint32_t)((wid*16 + (lane&15))*ASTRIDE*2) + (uint32_t)((lane>>4)*16);
        uint32_t aLoBase   = uAlo + (uint32_t)((wid*16 + (lane&15))*ASTRIDE*2) + (uint32_t)((lane>>4)*16);

        for(int ch=0; ch<8; ch++){
            int k0 = ch*32;
            // load A hi/lo: 128 rows x 32 bf16 = 512 x 16B units -> 2 units/thread/buffer
            #pragma unroll
            for(int g=0;g<2;g++){
                int j = tid + g*256;
                int row = j>>2, c16 = j&3;
                int doff = row*ASTRIDE + c16*8;
                long soff = (long)(m0+row)*EDGE + k0 + c16*8;
                *(uint4*)(sAhi + doff) = *(const uint4*)(hHi + soff);
                *(uint4*)(sAlo + doff) = *(const uint4*)(hLo + soff);
            }
            // load B hi/lo: 64 rows x 32 bf16 = 256 units -> 1/thread/buffer
            {
                int row = tid>>2, c16 = tid&3;
                int doff = row*ASTRIDE + c16*8;
                long soff = (long)(g0+row)*EDGE + k0 + c16*8;
                *(uint4*)(sBhi + doff) = *(const uint4*)(d_WNHi + soff);
                *(uint4*)(sBlo + doff) = *(const uint4*)(d_WNLo + soff);
            }
            __syncthreads();
            #pragma unroll
            for(int ktl=0; ktl<2; ktl++){
                uint32_t koff = ktl*32;
                uint32_t ah0,ah1,ah2,ah3, al0,al1,al2,al3;
                LDMX4(ah0,ah1,ah2,ah3, aAddrBase + koff);
                LDMX4(al0,al1,al2,al3, aLoBase + koff);
                #pragma unroll
                for(int jg=0; jg<4; jg++){
                    uint32_t bAddr = uBhi + (uint32_t)((jg*16 + (lane&15))*ASTRIDE*2) + (uint32_t)((lane>>4)*16) + koff;
                    uint32_t bLoAddr = uBlo + (uint32_t)((jg*16 + (lane&15))*ASTRIDE*2) + (uint32_t)((lane>>4)*16) + koff;
                    uint32_t bh0,bh1,bh2,bh3, bl0,bl1,bl2,bl3;
                    LDMX4(bh0,bh1,bh2,bh3, bAddr);
                    LDMX4(bl0,bl1,bl2,bl3, bLoAddr);
                    int j0 = jg*2, j1 = jg*2+1;
                    MMA16816(C[j0][0],C[j0][1],C[j0][2],C[j0][3], ah0,ah1,ah2,ah3, bh0,bh2);
                    MMA16816(C[j0][0],C[j0][1],C[j0][2],C[j0][3], ah0,ah1,ah2,ah3, bl0,bl2);
                    MMA16816(C[j0][0],C[j0][1],C[j0][2],C[j0][3], al0,al1,al2,al3, bh0,bh2);
                    MMA16816(C[j1][0],C[j1][1],C[j1][2],C[j1][3], ah0,ah1,ah2,ah3, bh1,bh3);
                    MMA16816(C[j1][0],C[j1][1],C[j1][2],C[j1][3], ah0,ah1,ah2,ah3, bl1,bl3);
                    MMA16816(C[j1][0],C[j1][1],C[j1][2],C[j1][3], al0,al1,al2,al3, bh1,bh3);
                }
            }
            __syncthreads();
        }

        // wait for the small-work block
        if(tid==0){ while(atomicAdd(&d_flag,0) < t){} }
        __syncthreads();
        __threadfence();
        int gate_n = d_gateNt[t];

        // exchange: pair lanes (tig even/odd) to reunite 4 gates per cell
        float P[8][4];
        #pragma unroll
        for(int j=0;j<8;j++){
            P[j][0] = __shfl_xor_sync(0xffffffffu, C[j][0], 1);
            P[j][1] = __shfl_xor_sync(0xffffffffu, C[j][1], 1);
            P[j][2] = __shfl_xor_sync(0xffffffffu, C[j][2], 1);
            P[j][3] = __shfl_xor_sync(0xffffffffu, C[j][3], 1);
        }
        if((tig & 1) == 0){
            int r0 = m0 + wid*16 + gid;
            int r1 = r0 + 8;
            int off0 = (r0*TOBS+tc)*2, off1 = (r1*TOBS+tc)*2;
            float x00=nstep_in[off0], x01=nstep_in[off0+1];
            float x10=nstep_in[off1], x11=nstep_in[off1+1];
            bool mv0 = obs ? (nhist[r0] > (TOBS - t)) : true;
            bool mv1 = obs ? (nhist[r1] > (TOBS - t)) : true;
            bool un0 = gate_n && mv0, un1 = gate_n && mv1;
            float wv0 = d_w[r0], wv1 = d_w[r1];
            int hn0 = (r0/KK)*EDGE, hn1 = (r1/KK)*EDGE;
            #pragma unroll
            for(int j=0;j<8;j++){
                int e = e0c + 2*j + (tig>>1);
                int gb = g0 + 8*j + (tig>>1)*4;
                float wx0[4], wx1[4];
                #pragma unroll
                for(int q=0;q<4;q++){
                    float w0q = d_WxN[(gb+q)*2], w1q = d_WxN[(gb+q)*2+1], bq = d_bN[gb+q];
                    wx0[q] = x00*w0q + x01*w1q + bq;
                    wx1[q] = x10*w0q + x11*w1q + bq;
                }
                // row r0: gates {C[j][0], C[j][1], P[j][0], P[j][1]}
                {
                    float g4[4] = {C[j][0]+wx0[0], C[j][1]+wx0[1], P[j][0]+wx0[2], P[j][1]+wx0[3]};
                    float ig=sigm(g4[0]), fg=sigm(g4[1]), gg=tanhf(g4[2]), og=sigm(g4[3]);
                    long idx = (long)r0*EDGE + e;
                    float c2 = fg*d_nct[idx] + ig*gg;
                    float hv;
                    __nv_bfloat16 hb, lb;
                    if(un0){
                        d_nct[idx]=c2;
                        hv = og*tanhf(c2);
                        hb = __float2bfloat16(hv);
                        lb = __float2bfloat16(hv - __bfloat162float(hb));
                    }else{
                        hb = hHi[idx]; lb = hLo[idx];
                        hv = __bfloat162float(hb) + __bfloat162float(lb);
                    }
                    d_nhHi[nxt][idx]=hb; d_nhLo[nxt][idx]=lb;
                    if(gate_n && wv0 != 0.f) atomicAdd(&d_Htacc[hn0+e], wv0*hv);
                }
                // row r1: gates {C[j][2], C[j][3], P[j][2], P[j][3]}
                {
                    float g4[4] = {C[j][2]+wx1[0], C[j][3]+wx1[1], P[j][2]+wx1[2], P[j][3]+wx1[3]};
                    float ig=sigm(g4[0]), fg=sigm(g4[1]), gg=tanhf(g4[2]), og=sigm(g4[3]);
                    long idx = (long)r1*EDGE + e;
                    float c2 = fg*d_nct[idx] + ig*gg;
                    float hv;
                    __nv_bfloat16 hb, lb;
                    if(un1){
                        d_nct[idx]=c2;
                        hv = og*tanhf(c2);
                        hb = __float2bfloat16(hv);
                        lb = __float2bfloat16(hv - __bfloat162float(hb));
                    }else{
                        hb = hHi[idx]; lb = hLo[idx];
                        hv = __bfloat162float(hb) + __bfloat162float(lb);
                    }
                    d_nhHi[nxt][idx]=hb; d_nhLo[nxt][idx]=lb;
                    if(gate_n && wv1 != 0.f) atomicAdd(&d_Htacc[hn1+e], wv1*hv);
                }
            }
        }
        return;
    }

    // ================= target: SIMT FMA2 GEMM + LSTM (tiny) =================
    {
        float (*As)[68]  = (float(*)[68]) (dsm);
        float (*Bs)[140] = (float(*)[140])(dsm + sizeof(float)*32*68);
        int bj = bx - 385;
        int g0 = bj*128, e0 = bj*32;
        const float* A = d_thtT[cur];
        int ty = tid>>4, tx = tid&15;
        int pb = tx*8; pb += (pb>>5)<<2;
        ULL accp[4][4];
        #pragma unroll
        for(int i=0;i<4;i++){
            #pragma unroll
            for(int j=0;j<4;j++) accp[i][j]=0ull;
        }
        for(int kt=0; kt<NODE; kt+=32){
            #pragma unroll
            for(int g=0;g<2;g++){
                int idx = tid + g*256;
                int k = idx>>4, nq = (idx&15)*4;
                *(float4*)&As[k][nq] = *(const float4*)&A[(kt+k)*NN + nq];
            }
            #pragma unroll
            for(int g=0;g<4;g++){
                int idx = tid + g*256;
                int k = idx>>5, cq = (idx&31)*4;
                int pc = cq + ((cq>>5)<<2);
                *(float4*)&Bs[k][pc] = *(const float4*)&d_WhhTT[(kt+k)*GT + g0+cq];
            }
            __syncthreads();
            #pragma unroll
            for(int k=0;k<32;k++){
                float4 a0 = *(const float4*)&As[k][ty*4];
                ulonglong2 bb0 = *(const ulonglong2*)&Bs[k][pb];
                ulonglong2 bb1 = *(const ulonglong2*)&Bs[k][pb+4];
                ULL ap;
                PK(ap,a0.x); FMA2(accp[0][0],ap,bb0.x); FMA2(accp[0][1],ap,bb0.y); FMA2(accp[0][2],ap,bb1.x); FMA2(accp[0][3],ap,bb1.y);
                PK(ap,a0.y); FMA2(accp[1][0],ap,bb0.x); FMA2(accp[1][1],ap,bb0.y); FMA2(accp[1][2],ap,bb1.x); FMA2(accp[1][3],ap,bb1.y);
                PK(ap,a0.z); FMA2(accp[2][0],ap,bb0.x); FMA2(accp[2][1],ap,bb0.y); FMA2(accp[2][2],ap,bb1.x); FMA2(accp[2][3],ap,bb1.y);
                PK(ap,a0.w); FMA2(accp[3][0],ap,bb0.x); FMA2(accp[3][1],ap,bb0.y); FMA2(accp[3][2],ap,bb1.x); FMA2(accp[3][3],ap,bb1.y);
            }
            __syncthreads();
        }
        if(tid==0){ while(atomicAdd(&d_flag,0) < t){} }
        __syncthreads();
        __threadfence();
        int gate_t = d_gateTt[t];
        #pragma unroll
        for(int i=0;i<4;i++){
            int n = ty*4 + i;
            float x0=d_cstep[n*2], x1=d_cstep[n*2+1];
            bool tm = obs ? (thist[n] > (TOBS - t)) : true;
            #pragma unroll
            for(int c=0;c<2;c++){
                float g4[4];
                UPK(g4[0],g4[1],accp[i][c*2]);
                UPK(g4[2],g4[3],accp[i][c*2+1]);
                int rr = g0 + tx*8 + c*4;
                #pragma unroll
                for(int q=0;q<4;q++)
                    g4[q] += x0*d_WxT[(rr+q)*2] + x1*d_WxT[(rr+q)*2+1] + d_bT[rr+q];
                float ig=sigm(g4[0]), fg=sigm(g4[1]), gg=tanhf(g4[2]), og=sigm(g4[3]);
                int e = e0 + tx*2 + c;
                float cold = d_tct[n*NODE+e];
                float c2 = fg*cold + ig*gg;
                float h2 = og*tanhf(c2);
                bool un = gate_t && tm;
                float hv;
                if(un){ d_tct[n*NODE+e]=c2; hv=h2; }
                else  { hv = d_thtT[cur][e*NN+n]; }
                d_thtT[nxt][e*NN+n]=hv;
            }
        }
    }
}

// ---------------- launch ----------------
extern "C" void kernel_launch(void* const* d_in, const int* in_sizes, int n_in,
                              void* d_out, int out_size)
{
    const float* img    = (const float*)d_in[0];
    const float* tabs   = (const float*)d_in[1];
    const float* trel   = (const float*)d_in[2];
    const float* tstep  = (const float*)d_in[3];
    const float* nabs   = (const float*)d_in[4];
    const float* nstep  = (const float*)d_in[6];
    const int*   thist  = (const int*)d_in[7];
    const int*   nhist  = (const int*)d_in[8];
    const float* W_disp = (const float*)d_in[9];
    const float* b_disp = (const float*)d_in[10];
    const float* Wih_t  = (const float*)d_in[11];
    const float* Whh_t  = (const float*)d_in[12];
    const float* bih_t  = (const float*)d_in[13];
    const float* bhh_t  = (const float*)d_in[14];
    const float* Wih_n  = (const float*)d_in[15];
    const float* Whh_n  = (const float*)d_in[16];
    const float* bih_n  = (const float*)d_in[17];
    const float* bhh_n  = (const float*)d_in[18];
    const float* W_att_t= (const float*)d_in[19];
    const float* b_att_t= (const float*)d_in[20];
    const float* W_att_n= (const float*)d_in[21];
    const float* b_att_n= (const float*)d_in[22];
    const float* W_pred = (const float*)d_in[23];
    const float* b_pred = (const float*)d_in[24];
    float* out = (float*)d_out;

    k_zero<<<256,256>>>();
    k_tables<<<TSTEPS-1,256>>>(thist,nhist);
    k_prep<<<256,256>>>(Whh_n,Wih_n,bih_n,bhh_n,Whh_t,Wih_t,bih_t,bhh_t,
                        W_disp,b_disp,img,W_pred);
    for(int t=1; t<TSTEPS; t++){
        k_step<<<389,256,DSMEM_TOTAL>>>(t,tabs,trel,tstep,nabs,nstep,thist,nhist,
                            W_att_t,b_att_t,W_att_n,b_att_n,W_pred,b_pred,out);
    }
}

// round 7
// speedup vs baseline: 1.0328x; 1.0328x over previous
#include <cuda_runtime.h>
#include <cuda_bf16.h>
#include <math.h>
#include <stdint.h>

#define NN    64
#define KK    48
#define MM    (NN*KK)      // 3072
#define TOBS  30
#define PREDN 15
#define TSTEPS (TOBS+PREDN)  // 45, t runs 1..44
#define EMB   64
#define NODE  128
#define EDGE  256
#define CNN   512
#define GT    (4*NODE)     // 512
#define GN    (4*EDGE)     // 1024
#define CONC  (NODE+CNN+EDGE) // 896
#define NBLK  389

typedef unsigned long long ULL;

// f32x2 packed math for the (small) target SIMT GEMM
#define PK(d,s)   asm("mov.b64 %0, {%1, %1};" : "=l"(d) : "f"(s))
#define UPK(lo,hi,p) asm("mov.b64 {%0, %1}, %2;" : "=f"(lo), "=f"(hi) : "l"(p))
#define FMA2(c,a,b) asm("fma.rn.f32x2 %0, %1, %2, %0;" : "+l"(c) : "l"(a), "l"(b))

__device__ __forceinline__ uint32_t smem_u32(const void* p){
    uint32_t a; asm("{ .reg .u64 t; cvta.to.shared.u64 t, %1; cvt.u32.u64 %0, t; }" : "=r"(a) : "l"(p)); return a;
}
#define LDMX4(r0,r1,r2,r3,addr) \
    asm volatile("ldmatrix.sync.aligned.m8n8.x4.shared.b16 {%0,%1,%2,%3}, [%4];" \
        : "=r"(r0), "=r"(r1), "=r"(r2), "=r"(r3) : "r"(addr))
#define MMA16816(c,a0,a1,a2,a3,b0,b1) \
    asm volatile("mma.sync.aligned.m16n8k16.row.col.f32.bf16.bf16.f32 " \
        "{%0,%1,%2,%3}, {%4,%5,%6,%7}, {%8,%9}, {%0,%1,%2,%3};" \
        : "+f"((c)[0]), "+f"((c)[1]), "+f"((c)[2]), "+f"((c)[3]) \
        : "r"(a0), "r"(a1), "r"(a2), "r"(a3), "r"(b0), "r"(b1))

// ---------------- persistent device state ----------------
__device__ float d_thtT[2][NODE*NN];          // target h, transposed [e][n], fp32
__device__ float d_tct[NN*NODE];
__device__ __nv_bfloat16 d_nhHi[2][MM*EDGE];  // nearby h split bf16, [m][e]
__device__ __nv_bfloat16 d_nhLo[2][MM*EDGE];
__device__ float d_nct[MM*EDGE];
__device__ float d_Ht[NN*EDGE];
__device__ float d_Htacc[NN*EDGE];
__device__ float d_cabs[NN*2], d_crel[NN*2], d_cstep[NN*2];
__device__ float d_w[MM];
__device__ int   d_flag;
__device__ unsigned d_barCnt;
__device__ unsigned d_barGen;
__device__ int   d_gateTt[TSTEPS];
__device__ int   d_gateNt[TSTEPS];
__device__ float d_currNt[TSTEPS];
// weights
__device__ __nv_bfloat16 d_WNHi[GN*EDGE];     // nearby Whh gate-interleaved [g][k], split bf16
__device__ __nv_bfloat16 d_WNLo[GN*EDGE];
__device__ float d_WhhTT[NODE*GT];            // target Whh transposed [k][g] fp32
__device__ float d_WxN[GN*2], d_bN[GN];
__device__ float d_WxT[GT*2], d_bT[GT];
__device__ float d_imgpart[NN*2];

__device__ __forceinline__ float sigm(float x){ return 1.f/(1.f+expf(-x)); }

// device-wide sense barrier (all NBLK blocks resident by construction)
__device__ __forceinline__ void gbar(){
    __syncthreads();
    if(threadIdx.x==0){
        __threadfence();
        unsigned g = *((volatile unsigned*)&d_barGen);
        if(atomicAdd(&d_barCnt,1u) == NBLK-1u){
            d_barCnt = 0u;
            __threadfence();
            atomicExch(&d_barGen, g+1u);
        }else{
            while(*((volatile unsigned*)&d_barGen) == g){}
        }
        __threadfence();
    }
    __syncthreads();
}

// dynamic smem layout for nearby path (bf16, padded rows: 40 elems = 80B)
#define ASTRIDE 40
#define OFF_AHI 0
#define OFF_ALO 10240
#define OFF_BHI 20480
#define OFF_BLO 25600
#define DSMEM_TOTAL 30720

// ---------------- init kernels ----------------
__global__ void k_zero(){
    long i0 = (long)blockIdx.x*blockDim.x + threadIdx.x;
    long st = (long)gridDim.x*blockDim.x;
    uint32_t* hh = (uint32_t*)&d_nhHi[0][0];
    uint32_t* hl = (uint32_t*)&d_nhLo[0][0];
    for(long i=i0;i<(long)MM*EDGE;i+=st){ hh[i]=0u; hl[i]=0u; } // covers both [2][..] bufs
    for(long i=i0;i<(long)MM*EDGE;i+=st) d_nct[i]=0.f;
    float* th = &d_thtT[0][0];
    for(long i=i0;i<2L*NN*NODE;i+=st) th[i]=0.f;
    for(long i=i0;i<(long)NN*NODE;i+=st) d_tct[i]=0.f;
    for(long i=i0;i<(long)NN*EDGE;i+=st){ d_Ht[i]=0.f; d_Htacc[i]=0.f; }
    if(i0<NN*2){ d_cabs[i0]=0.f; d_crel[i0]=0.f; d_cstep[i0]=0.f; }
    if(i0==0){ d_flag=0; d_barCnt=0u; d_barGen=0u; }
}

__global__ void k_tables(const int* __restrict__ thist, const int* __restrict__ nhist){
    int t = blockIdx.x + 1;
    int tid = threadIdx.x;
    __shared__ int s_cnt[256];
    __shared__ int s_any[256];
    int cnt=0, any=0;
    if(t < TOBS){
        for(int m=tid;m<MM;m+=256) cnt += (nhist[m] > (TOBS - t)) ? 1 : 0;
        for(int n=tid;n<NN;n+=256) any |= (thist[n] > (TOBS - t)) ? 1 : 0;
    }else{
        cnt = (tid==0)?MM:0; any = 1;
    }
    s_cnt[tid]=cnt; s_any[tid]=any;
    __syncthreads();
    for(int o=128;o>0;o>>=1){
        if(tid<o){ s_cnt[tid]+=s_cnt[tid+o]; s_any[tid]|=s_any[tid+o]; }
        __syncthreads();
    }
    if(tid==0){
        int gt = s_any[0]?1:0;
        int cn = s_cnt[0];
        d_gateTt[t]=gt; d_gateNt[t]=(gt && cn>0)?1:0; d_currNt[t]=(float)cn;
    }
}

__global__ void k_prep(const float* __restrict__ Whh_n, const float* __restrict__ Wih_n,
                       const float* __restrict__ bih_n, const float* __restrict__ bhh_n,
                       const float* __restrict__ Whh_t, const float* __restrict__ Wih_t,
                       const float* __restrict__ bih_t, const float* __restrict__ bhh_t,
                       const float* __restrict__ W_disp, const float* __restrict__ b_disp,
                       const float* __restrict__ img, const float* __restrict__ W_pred){
    int i0 = blockIdx.x*blockDim.x + threadIdx.x;
    int st = gridDim.x*blockDim.x;
    for(int i=i0;i<GN*EDGE;i+=st){
        int g=i/EDGE, k=i%EDGE; int e=g>>2, q=g&3;
        float v = Whh_n[(q*EDGE+e)*EDGE + k];
        __nv_bfloat16 hi = __float2bfloat16(v);
        d_WNHi[i] = hi;
        d_WNLo[i] = __float2bfloat16(v - __bfloat162float(hi));
    }
    for(int i=i0;i<NODE*GT;i+=st){
        int k=i/GT, g=i%GT; int e=g>>2, q=g&3;
        d_WhhTT[i] = Whh_t[(q*NODE+e)*NODE + k];
    }
    for(int r=i0;r<GN;r+=st){
        int e=r>>2, q=r&3; int o=q*EDGE+e;
        float w0=0.f,w1=0.f,bb=bih_n[o]+bhh_n[o];
        for(int d=0;d<EMB;d++){
            float wi=Wih_n[o*EMB+d];
            w0+=wi*W_disp[d*2]; w1+=wi*W_disp[d*2+1]; bb+=wi*b_disp[d];
        }
        d_WxN[r*2]=w0; d_WxN[r*2+1]=w1; d_bN[r]=bb;
    }
    for(int r=i0;r<GT;r+=st){
        int e=r>>2, q=r&3; int o=q*NODE+e;
        float w0=0.f,w1=0.f,bb=bih_t[o]+bhh_t[o];
        for(int d=0;d<EMB;d++){
            float wi=Wih_t[o*EMB+d];
            w0+=wi*W_disp[d*2]; w1+=wi*W_disp[d*2+1]; bb+=wi*b_disp[d];
        }
        d_WxT[r*2]=w0; d_WxT[r*2+1]=w1; d_bT[r]=bb;
    }
    for(int i=i0;i<NN*2;i+=st){
        int n=i>>1, j=i&1; float s=0.f;
        for(int c=0;c<CNN;c++) s += img[n*CNN+c]*W_pred[j*CONC + NODE + c];
        d_imgpart[i]=s;
    }
}

// =========================================================================
// ONE persistent kernel: loops t=1..44 with device-wide barrier per step.
// bx==0: small serial work (publishes d_flag=t).
// bx 1..384: nearby mma.sync split-bf16 GEMM + fused LSTM (warp tile 32x32)
// bx 385..388: target SIMT GEMM+LSTM.
// =========================================================================
__global__ void __launch_bounds__(256,3) k_run(
    const float* __restrict__ tabs, const float* __restrict__ trel, const float* __restrict__ tstep,
    const float* __restrict__ nabs_in, const float* __restrict__ nstep_in,
    const int* __restrict__ thist, const int* __restrict__ nhist,
    const float* __restrict__ W_att_t, const float* __restrict__ b_att_t,
    const float* __restrict__ W_att_n, const float* __restrict__ b_att_n,
    const float* __restrict__ W_pred, const float* __restrict__ b_pred,
    float* __restrict__ out)
{
    extern __shared__ __align__(128) char dsm[];
    const int bx = blockIdx.x;
    const int tid = threadIdx.x;

    // hoisted nearby-path constants
    const int bi = bx-1;
    const int rowTile = (bi>=0) ? (bi % 24) : 0;
    const int colTile = (bi>=0) ? (bi / 24) : 0;
    const int m0 = rowTile*128, g0 = colTile*64, e0c = colTile*16;
    const int wid = tid>>5, lane = tid&31;
    const int tig = lane&3, gid = lane>>2;
    const int wm = wid&3, wn = wid>>2;           // 4 M-warps x 2 N-warps
    __nv_bfloat16* sAhi = (__nv_bfloat16*)(dsm + OFF_AHI);
    __nv_bfloat16* sAlo = (__nv_bfloat16*)(dsm + OFF_ALO);
    __nv_bfloat16* sBhi = (__nv_bfloat16*)(dsm + OFF_BHI);
    __nv_bfloat16* sBlo = (__nv_bfloat16*)(dsm + OFF_BLO);
    const uint32_t uAhi = smem_u32(sAhi), uAlo = smem_u32(sAlo);
    const uint32_t uBhi = smem_u32(sBhi), uBlo = smem_u32(sBlo);
    const uint32_t aHiB = uAhi + (uint32_t)((wm*32 + (lane&15))*ASTRIDE*2) + (uint32_t)((lane>>4)*16);
    const uint32_t aLoB = uAlo + (uint32_t)((wm*32 + (lane&15))*ASTRIDE*2) + (uint32_t)((lane>>4)*16);
    const uint32_t bHiB = uBhi + (uint32_t)((wn*32 + (lane&15))*ASTRIDE*2) + (uint32_t)((lane>>4)*16);
    const uint32_t bLoB = uBlo + (uint32_t)((wn*32 + (lane&15))*ASTRIDE*2) + (uint32_t)((lane>>4)*16);

    for(int t=1; t<TSTEPS; t++){
        const int cur=(t-1)&1, nxt=t&1;
        const bool obs = (t < TOBS);
        const int tc = obs ? t : (TOBS-1);

        if(bx == 0){
            // ------------- small serial work -------------
            __shared__ float s_pred[NN*2];
            int gate_n_prev = (t>=2) ? d_gateNt[t-1] : 0;
            for(int i=tid;i<NN*EDGE;i+=256){
                if(gate_n_prev) d_Ht[i]=d_Htacc[i];
                d_Htacc[i]=0.f;
            }
            __syncthreads();
            if(!obs){
                int item = tid>>1, sub = tid&1;
                int n = item>>1, j = item&1;
                const float* wp = &W_pred[j*CONC];
                const float* hh = &d_Ht[n*EDGE];
                float acc = 0.f;
                for(int e=sub*64;e<sub*64+64;e++) acc += d_thtT[cur][e*NN+n]*wp[e];
                for(int e=sub*128;e<sub*128+128;e++) acc += hh[e]*wp[NODE+CNN+e];
                acc += __shfl_xor_sync(0xffffffffu, acc, 1);
                if(sub==0) s_pred[item] = acc + d_imgpart[item] + b_pred[j];
            }
            __syncthreads();
            if(obs){
                if(tid<NN*2){
                    int n=tid>>1, j=tid&1; int off=(n*TOBS+t)*2+j;
                    d_cabs[tid]=tabs[off]; d_crel[tid]=trel[off]; d_cstep[tid]=tstep[off];
                }
            }else{
                if(tid<NN*2){
                    float p=s_pred[tid];
                    d_cabs[tid]+=p;
                    float cr=d_crel[tid]+p; d_crel[tid]=cr;
                    d_cstep[tid]=p;
                    int n=tid>>1, j=tid&1;
                    out[(n*PREDN + (t-TOBS))*2 + j] = cr;
                }
            }
            __syncthreads();
            float currNf = d_currNt[t];
            int n = tid>>2, s = tid&3;
            float crel0=d_crel[n*2], crel1=d_crel[n*2+1];
            float p0=0.f,p1=0.f,p2=0.f;
            for(int a=s*16;a<s*16+16;a++){
                float atv = W_att_t[a*2]*crel0 + W_att_t[a*2+1]*crel1 + b_att_t[a];
                p0 += atv*W_att_n[a*2];
                p1 += atv*W_att_n[a*2+1];
                p2 += atv*b_att_n[a];
            }
            #pragma unroll
            for(int o=1;o<4;o<<=1){
                p0 += __shfl_xor_sync(0xffffffffu,p0,o);
                p1 += __shfl_xor_sync(0xffffffffu,p1,o);
                p2 += __shfl_xor_sync(0xffffffffu,p2,o);
            }
            float cab0=d_cabs[n*2], cab1=d_cabs[n*2+1];
            float sc[12], mf[12];
            #pragma unroll
            for(int kk=0;kk<12;kk++){
                int m = n*KK + s*12+kk;
                int off = (m*TOBS+tc)*2;
                float dx=nabs_in[off]-cab0, dy=nabs_in[off+1]-cab1;
                float mv = obs ? ((nhist[m] > (TOBS - t)) ? 1.f : 0.f) : 1.f;
                mf[kk]=mv;
                sc[kk]=(dx*p0+dy*p1+p2)*currNf*0.125f*mv;
            }
            float mx = sc[0];
            #pragma unroll
            for(int kk=1;kk<12;kk++) mx=fmaxf(mx,sc[kk]);
            #pragma unroll
            for(int o=1;o<4;o<<=1) mx = fmaxf(mx, __shfl_xor_sync(0xffffffffu,mx,o));
            float dn = 0.f;
            #pragma unroll
            for(int kk=0;kk<12;kk++) dn += expf(sc[kk]-mx)*mf[kk];
            #pragma unroll
            for(int o=1;o<4;o<<=1) dn += __shfl_xor_sync(0xffffffffu,dn,o);
            dn += 1e-6f;
            #pragma unroll
            for(int kk=0;kk<12;kk++){
                int m = n*KK + s*12+kk;
                d_w[m] = expf(sc[kk]-mx)*mf[kk]/dn;
            }
            __threadfence();
            __syncthreads();
            if(tid==0) atomicExch(&d_flag, t);
        }
        else if(bx <= 384){
            // ============ nearby: mma.sync split-bf16, warp tile 32x32 ============
            const __nv_bfloat16* hHi = d_nhHi[cur];
            const __nv_bfloat16* hLo = d_nhLo[cur];
            float C[2][4][4];
            #pragma unroll
            for(int mi=0;mi<2;mi++)
                #pragma unroll
                for(int j=0;j<4;j++){ C[mi][j][0]=0.f; C[mi][j][1]=0.f; C[mi][j][2]=0.f; C[mi][j][3]=0.f; }

            for(int ch=0; ch<8; ch++){
                int k0 = ch*32;
                #pragma unroll
                for(int g=0;g<2;g++){
                    int j = tid + g*256;
                    int row = j>>2, c16 = j&3;
                    int doff = row*ASTRIDE + c16*8;
                    long soff = (long)(m0+row)*EDGE + k0 + c16*8;
                    *(uint4*)(sAhi + doff) = *(const uint4*)(hHi + soff);
                    *(uint4*)(sAlo + doff) = *(const uint4*)(hLo + soff);
                }
                {
                    int row = tid>>2, c16 = tid&3;
                    int doff = row*ASTRIDE + c16*8;
                    long soff = (long)(g0+row)*EDGE + k0 + c16*8;
                    *(uint4*)(sBhi + doff) = *(const uint4*)(d_WNHi + soff);
                    *(uint4*)(sBlo + doff) = *(const uint4*)(d_WNLo + soff);
                }
                __syncthreads();
                #pragma unroll
                for(int ktl=0; ktl<2; ktl++){
                    uint32_t koff = ktl*32;
                    uint32_t ah[2][4], al[2][4];
                    #pragma unroll
                    for(int mi=0;mi<2;mi++){
                        LDMX4(ah[mi][0],ah[mi][1],ah[mi][2],ah[mi][3], aHiB + (uint32_t)(mi*16*ASTRIDE*2) + koff);
                        LDMX4(al[mi][0],al[mi][1],al[mi][2],al[mi][3], aLoB + (uint32_t)(mi*16*ASTRIDE*2) + koff);
                    }
                    #pragma unroll
                    for(int ng=0; ng<2; ng++){
                        uint32_t bh0,bh1,bh2,bh3, bl0,bl1,bl2,bl3;
                        LDMX4(bh0,bh1,bh2,bh3, bHiB + (uint32_t)(ng*16*ASTRIDE*2) + koff);
                        LDMX4(bl0,bl1,bl2,bl3, bLoB + (uint32_t)(ng*16*ASTRIDE*2) + koff);
                        #pragma unroll
                        for(int mi=0;mi<2;mi++){
                            MMA16816(C[mi][ng*2],   ah[mi][0],ah[mi][1],ah[mi][2],ah[mi][3], bh0,bh2);
                            MMA16816(C[mi][ng*2],   ah[mi][0],ah[mi][1],ah[mi][2],ah[mi][3], bl0,bl2);
                            MMA16816(C[mi][ng*2],   al[mi][0],al[mi][1],al[mi][2],al[mi][3], bh0,bh2);
                            MMA16816(C[mi][ng*2+1], ah[mi][0],ah[mi][1],ah[mi][2],ah[mi][3], bh1,bh3);
                            MMA16816(C[mi][ng*2+1], ah[mi][0],ah[mi][1],ah[mi][2],ah[mi][3], bl1,bl3);
                            MMA16816(C[mi][ng*2+1], al[mi][0],al[mi][1],al[mi][2],al[mi][3], bh1,bh3);
                        }
                    }
                }
                __syncthreads();
            }

            // wait for the small-work block
            if(tid==0){ while(*((volatile int*)&d_flag) < t){} }
            __syncthreads();
            __threadfence();
            int gate_n = d_gateNt[t];

            #pragma unroll
            for(int mi=0;mi<2;mi++){
                int r0 = m0 + wm*32 + mi*16 + gid;
                int r1 = r0 + 8;
                int off0 = (r0*TOBS+tc)*2, off1 = (r1*TOBS+tc)*2;
                float x00=nstep_in[off0], x01=nstep_in[off0+1];
                float x10=nstep_in[off1], x11=nstep_in[off1+1];
                bool mv0 = obs ? (nhist[r0] > (TOBS - t)) : true;
                bool mv1 = obs ? (nhist[r1] > (TOBS - t)) : true;
                bool un0 = gate_n && mv0, un1 = gate_n && mv1;
                float wv0 = d_w[r0], wv1 = d_w[r1];
                int hn0 = (r0/KK)*EDGE, hn1 = (r1/KK)*EDGE;
                #pragma unroll
                for(int j=0;j<4;j++){
                    float q0 = __shfl_xor_sync(0xffffffffu, C[mi][j][0], 1);
                    float q1 = __shfl_xor_sync(0xffffffffu, C[mi][j][1], 1);
                    float q2 = __shfl_xor_sync(0xffffffffu, C[mi][j][2], 1);
                    float q3 = __shfl_xor_sync(0xffffffffu, C[mi][j][3], 1);
                    if((tig & 1) == 0){
                        int e  = e0c + wn*8 + 2*j + (tig>>1);
                        int gb = g0 + wn*32 + 8*j + (tig>>1)*4;
                        float w0a=d_WxN[(gb+0)*2], w0b=d_WxN[(gb+0)*2+1], b0=d_bN[gb+0];
                        float w1a=d_WxN[(gb+1)*2], w1b=d_WxN[(gb+1)*2+1], b1=d_bN[gb+1];
                        float w2a=d_WxN[(gb+2)*2], w2b=d_WxN[(gb+2)*2+1], b2=d_bN[gb+2];
                        float w3a=d_WxN[(gb+3)*2], w3b=d_WxN[(gb+3)*2+1], b3=d_bN[gb+3];
                        // row r0: gates {C0, C1, q0, q1}
                        {
                            float ig=sigm(C[mi][j][0] + x00*w0a + x01*w0b + b0);
                            float fg=sigm(C[mi][j][1] + x00*w1a + x01*w1b + b1);
                            float gg=tanhf(q0 + x00*w2a + x01*w2b + b2);
                            float og=sigm(q1 + x00*w3a + x01*w3b + b3);
                            long idx = (long)r0*EDGE + e;
                            float c2 = fg*d_nct[idx] + ig*gg;
                            float hv; __nv_bfloat16 hb, lb;
                            if(un0){
                                d_nct[idx]=c2;
                                hv = og*tanhf(c2);
                                hb = __float2bfloat16(hv);
                                lb = __float2bfloat16(hv - __bfloat162float(hb));
                            }else{
                                hb = hHi[idx]; lb = hLo[idx];
                                hv = __bfloat162float(hb) + __bfloat162float(lb);
                            }
                            d_nhHi[nxt][idx]=hb; d_nhLo[nxt][idx]=lb;
                            if(gate_n && wv0 != 0.f) atomicAdd(&d_Htacc[hn0+e], wv0*hv);
                        }
                        // row r1: gates {C2, C3, q2, q3}
                        {
                            float ig=sigm(C[mi][j][2] + x10*w0a + x11*w0b + b0);
                            float fg=sigm(C[mi][j][3] + x10*w1a + x11*w1b + b1);
                            float gg=tanhf(q2 + x10*w2a + x11*w2b + b2);
                            float og=sigm(q3 + x10*w3a + x11*w3b + b3);
                            long idx = (long)r1*EDGE + e;
                            float c2 = fg*d_nct[idx] + ig*gg;
                            float hv; __nv_bfloat16 hb, lb;
                            if(un1){
                                d_nct[idx]=c2;
                                hv = og*tanhf(c2);
                                hb = __float2bfloat16(hv);
                                lb = __float2bfloat16(hv - __bfloat162float(hb));
                            }else{
                                hb = hHi[idx]; lb = hLo[idx];
                                hv = __bfloat162float(hb) + __bfloat162float(lb);
                            }
                            d_nhHi[nxt][idx]=hb; d_nhLo[nxt][idx]=lb;
                            if(gate_n && wv1 != 0.f) atomicAdd(&d_Htacc[hn1+e], wv1*hv);
                        }
                    }
                }
            }
        }
        else{
            // ================= target: SIMT FMA2 GEMM + LSTM (tiny) =================
            float (*As)[68]  = (float(*)[68]) (dsm);
            float (*Bs)[140] = (float(*)[140])(dsm + sizeof(float)*32*68);
            int bj = bx - 385;
            int g0t = bj*128, e0 = bj*32;
            const float* A = d_thtT[cur];
            int ty = tid>>4, tx = tid&15;
            int pb = tx*8; pb += (pb>>5)<<2;
            ULL accp[4][4];
            #pragma unroll
            for(int i=0;i<4;i++){
                #pragma unroll
                for(int j=0;j<4;j++) accp[i][j]=0ull;
            }
            for(int kt=0; kt<NODE; kt+=32){
                #pragma unroll
                for(int g=0;g<2;g++){
                    int idx = tid + g*256;
                    int k = idx>>4, nq = (idx&15)*4;
                    *(float4*)&As[k][nq] = *(const float4*)&A[(kt+k)*NN + nq];
                }
                #pragma unroll
                for(int g=0;g<4;g++){
                    int idx = tid + g*256;
                    int k = idx>>5, cq = (idx&31)*4;
                    int pc = cq + ((cq>>5)<<2);
                    *(float4*)&Bs[k][pc] = *(const float4*)&d_WhhTT[(kt+k)*GT + g0t+cq];
                }
                __syncthreads();
                #pragma unroll
                for(int k=0;k<32;k++){
                    float4 a0 = *(const float4*)&As[k][ty*4];
                    ulonglong2 bb0 = *(const ulonglong2*)&Bs[k][pb];
                    ulonglong2 bb1 = *(const ulonglong2*)&Bs[k][pb+4];
                    ULL ap;
                    PK(ap,a0.x); FMA2(accp[0][0],ap,bb0.x); FMA2(accp[0][1],ap,bb0.y); FMA2(accp[0][2],ap,bb1.x); FMA2(accp[0][3],ap,bb1.y);
                    PK(ap,a0.y); FMA2(accp[1][0],ap,bb0.x); FMA2(accp[1][1],ap,bb0.y); FMA2(accp[1][2],ap,bb1.x); FMA2(accp[1][3],ap,bb1.y);
                    PK(ap,a0.z); FMA2(accp[2][0],ap,bb0.x); FMA2(accp[2][1],ap,bb0.y); FMA2(accp[2][2],ap,bb1.x); FMA2(accp[2][3],ap,bb1.y);
                    PK(ap,a0.w); FMA2(accp[3][0],ap,bb0.x); FMA2(accp[3][1],ap,bb0.y); FMA2(accp[3][2],ap,bb1.x); FMA2(accp[3][3],ap,bb1.y);
                }
                __syncthreads();
            }
            if(tid==0){ while(*((volatile int*)&d_flag) < t){} }
            __syncthreads();
            __threadfence();
            int gate_t = d_gateTt[t];
            #pragma unroll
            for(int i=0;i<4;i++){
                int n = ty*4 + i;
                float x0=d_cstep[n*2], x1=d_cstep[n*2+1];
                bool tm = obs ? (thist[n] > (TOBS - t)) : true;
                #pragma unroll
                for(int c=0;c<2;c++){
                    float g4[4];
                    UPK(g4[0],g4[1],accp[i][c*2]);
                    UPK(g4[2],g4[3],accp[i][c*2+1]);
                    int rr = g0t + tx*8 + c*4;
                    #pragma unroll
                    for(int q=0;q<4;q++)
                        g4[q] += x0*d_WxT[(rr+q)*2] + x1*d_WxT[(rr+q)*2+1] + d_bT[rr+q];
                    float ig=sigm(g4[0]), fg=sigm(g4[1]), gg=tanhf(g4[2]), og=sigm(g4[3]);
                    int e = e0 + tx*2 + c;
                    float cold = d_tct[n*NODE+e];
                    float c2 = fg*cold + ig*gg;
                    float h2 = og*tanhf(c2);
                    bool un = gate_t && tm;
                    float hv;
                    if(un){ d_tct[n*NODE+e]=c2; hv=h2; }
                    else  { hv = d_thtT[cur][e*NN+n]; }
                    d_thtT[nxt][e*NN+n]=hv;
                }
            }
        }

        gbar();   // step boundary: all 389 blocks
    }
}

// ---------------- launch ----------------
extern "C" void kernel_launch(void* const* d_in, const int* in_sizes, int n_in,
                              void* d_out, int out_size)
{
    const float* img    = (const float*)d_in[0];
    const float* tabs   = (const float*)d_in[1];
    const float* trel   = (const float*)d_in[2];
    const float* tstep  = (const float*)d_in[3];
    const float* nabs   = (const float*)d_in[4];
    const float* nstep  = (const float*)d_in[6];
    const int*   thist  = (const int*)d_in[7];
    const int*   nhist  = (const int*)d_in[8];
    const float* W_disp = (const float*)d_in[9];
    const float* b_disp = (const float*)d_in[10];
    const float* Wih_t  = (const float*)d_in[11];
    const float* Whh_t  = (const float*)d_in[12];
    const float* bih_t  = (const float*)d_in[13];
    const float* bhh_t  = (const float*)d_in[14];
    const float* Wih_n  = (const float*)d_in[15];
    const float* Whh_n  = (const float*)d_in[16];
    const float* bih_n  = (const float*)d_in[17];
    const float* bhh_n  = (const float*)d_in[18];
    const float* W_att_t= (const float*)d_in[19];
    const float* b_att_t= (const float*)d_in[20];
    const float* W_att_n= (const float*)d_in[21];
    const float* b_att_n= (const float*)d_in[22];
    const float* W_pred = (const float*)d_in[23];
    const float* b_pred = (const float*)d_in[24];
    float* out = (float*)d_out;

    k_zero<<<256,256>>>();
    k_tables<<<TSTEPS-1,256>>>(thist,nhist);
    k_prep<<<256,256>>>(Whh_n,Wih_n,bih_n,bhh_n,Whh_t,Wih_t,bih_t,bhh_t,
                        W_disp,b_disp,img,W_pred);
    k_run<<<NBLK,256,DSMEM_TOTAL>>>(tabs,trel,tstep,nabs,nstep,thist,nhist,
                        W_att_t,b_att_t,W_att_n,b_att_n,W_pred,b_pred,out);
}